// round 13
// baseline (speedup 1.0000x reference)
#include <cuda_runtime.h>
#include <cuda_bf16.h>
#include <math.h>
#include <stdint.h>

#define NBLK   3
#define DM     512
#define DI     1024
#define DS     8
#define KC     4
#define LSEQ   2048
#define BATCH  4
#define NCLS   10
#define DTR    32
#define MROWS  (BATCH*LSEQ)
#define DXP    (DTR + 2*DS)
#define NCHUNK 16
#define LCH    (LSEQ/NCHUNK)
#define BD     (BATCH*DI)

__device__ float g_x[MROWS*DM];
__device__ float g_xz[MROWS*2*DI];
__device__ float g_u[MROWS*DI];
__device__ float g_delta[MROWS*DI];
__device__ float g_dbl[MROWS*DXP];
__device__ float g_ys[MROWS*DI];
__device__ float g_s[BD*NCHUNK*DS];
__device__ float g_hin[BD*NCHUNK*DS];
__device__ float g_dsum[BD*NCHUNK];
__device__ float g_pool4[4*BATCH*DM];
__device__ __nv_bfloat16 g_Ah[MROWS*DI];   // x splits (in_proj A)
__device__ __nv_bfloat16 g_Al[MROWS*DI];
__device__ __nv_bfloat16 g_Ch[MROWS*DI];   // ys splits (out_proj A)
__device__ __nv_bfloat16 g_Cl[MROWS*DI];
__device__ __nv_bfloat16 g_Bh[2*DI*DI];
__device__ __nv_bfloat16 g_Bl[2*DI*DI];
__device__ float g_pA2[128*192];
__device__ float g_pW2[192*128];
__device__ float g_pC2[128*128];
__device__ int   g_use_mma;

__device__ __forceinline__ float softplus_f(float v) {
    return (v > 20.f) ? v : log1pf(expf(v));
}
union F2U { unsigned long long u; float2 f; };
__device__ __forceinline__ float2 ffma2f(float2 d, float2 a, float2 b) {
    F2U dd, aa, bb; dd.f = d; aa.f = a; bb.f = b;
    asm("fma.rn.f32x2 %0, %1, %2, %0;" : "+l"(dd.u) : "l"(aa.u), "l"(bb.u));
    return dd.f;
}
__device__ __forceinline__ uint32_t smem_u32(const void* p) {
    uint32_t a;
    asm("{ .reg .u64 t; cvta.to.shared.u64 t, %1; cvt.u32.u64 %0, t; }" : "=r"(a) : "l"(p));
    return a;
}
__device__ __forceinline__ void mma16816(float* c, const uint32_t* a, const uint32_t* b) {
    asm volatile("mma.sync.aligned.m16n8k16.row.col.f32.bf16.bf16.f32 "
        "{%0,%1,%2,%3}, {%4,%5,%6,%7}, {%8,%9}, {%0,%1,%2,%3};"
        : "+f"(c[0]), "+f"(c[1]), "+f"(c[2]), "+f"(c[3])
        : "r"(a[0]), "r"(a[1]), "r"(a[2]), "r"(a[3]), "r"(b[0]), "r"(b[1]));
}
__device__ __forceinline__ void ldsm4(uint32_t* r, uint32_t addr) {
    asm volatile("ldmatrix.sync.aligned.m8n8.x4.shared.b16 {%0,%1,%2,%3}, [%4];"
        : "=r"(r[0]), "=r"(r[1]), "=r"(r[2]), "=r"(r[3]) : "r"(addr));
}

__device__ __forceinline__ void split2(float a, float b, __nv_bfloat162& h2, __nv_bfloat162& l2) {
    __nv_bfloat16 ha = __float2bfloat16(a), hb = __float2bfloat16(b);
    h2 = __nv_bfloat162(ha, hb);
    l2 = __nv_bfloat162(__float2bfloat16(a - __bfloat162float(ha)),
                        __float2bfloat16(b - __bfloat162float(hb)));
}

// copy x + (if mma) fused bf16 split of x
__global__ void copy_x_kernel(const float* __restrict__ x) {
    int i = blockIdx.x * 256 + threadIdx.x;
    float4 v = reinterpret_cast<const float4*>(x)[i];
    reinterpret_cast<float4*>(g_x)[i] = v;
    if (g_use_mma == 1) {
        __nv_bfloat162 h0, l0, h1, l1;
        split2(v.x, v.y, h0, l0);
        split2(v.z, v.w, h1, l1);
        __nv_bfloat162* ph = reinterpret_cast<__nv_bfloat162*>(g_Ah) + i * 2;
        __nv_bfloat162* pl = reinterpret_cast<__nv_bfloat162*>(g_Al) + i * 2;
        ph[0] = h0; ph[1] = h1; pl[0] = l0; pl[1] = l1;
    }
}

// standalone split (probe only)
__global__ void split_a_kernel(const float* __restrict__ in,
                               __nv_bfloat16* __restrict__ oh,
                               __nv_bfloat16* __restrict__ ol) {
    int i = blockIdx.x * 256 + threadIdx.x;
    float4 v = reinterpret_cast<const float4*>(in)[i];
    __nv_bfloat162 h0, l0, h1, l1;
    split2(v.x, v.y, h0, l0);
    split2(v.z, v.w, h1, l1);
    __nv_bfloat162* ph = reinterpret_cast<__nv_bfloat162*>(oh) + i * 2;
    __nv_bfloat162* pl = reinterpret_cast<__nv_bfloat162*>(ol) + i * 2;
    ph[0] = h0; ph[1] = h1; pl[0] = l0; pl[1] = l1;
}
// W[K][N] fp32 -> hi/lo bf16 [N][K]
__global__ void split_bt_kernel(const float* __restrict__ W, int K, int N,
                                __nv_bfloat16* __restrict__ oh,
                                __nv_bfloat16* __restrict__ ol, int force) {
    if (!force && g_use_mma != 1) return;
    __shared__ float tile[32][33];
    int tx = threadIdx.x, ty = threadIdx.y;
    int n0 = blockIdx.x * 32, k0 = blockIdx.y * 32;
#pragma unroll
    for (int j = 0; j < 4; j++)
        tile[ty + j * 8][tx] = W[(size_t)(k0 + ty + j * 8) * N + n0 + tx];
    __syncthreads();
#pragma unroll
    for (int j = 0; j < 4; j++) {
        int n = n0 + ty + j * 8;
        float v = tile[tx][ty + j * 8];
        __nv_bfloat16 h = __float2bfloat16(v);
        oh[(size_t)n * K + k0 + tx] = h;
        ol[(size_t)n * K + k0 + tx] = __float2bfloat16(v - __bfloat162float(h));
    }
}

// ---- HMMA bf16x3 GEMM (R11-proven single-buffer version) ----
// CTA 128x128, BK=32. 8 warps as 4(m) x 2(n): each warp 32x64.
#define SPAD 40
template<int RES, int WS>
__global__ __launch_bounds__(256) void hmma_gemm(int K, int N,
        const __nv_bfloat16* __restrict__ Ah, const __nv_bfloat16* __restrict__ Al,
        const __nv_bfloat16* __restrict__ Bh, const __nv_bfloat16* __restrict__ Bl,
        float* __restrict__ C,
        __nv_bfloat16* __restrict__ Oh, __nv_bfloat16* __restrict__ Ol, int force)
{
    if (!force && g_use_mma != 1) return;
    __shared__ __nv_bfloat16 sA[2][128][SPAD];
    __shared__ __nv_bfloat16 sB[2][128][SPAD];
    const int t = threadIdx.x;
    const int wid = t >> 5, lane = t & 31;
    const int warp_m = wid & 3, warp_n = wid >> 2;
    const int m0 = blockIdx.y * 128, n0 = blockIdx.x * 128;

    float acc[2][8][4];
#pragma unroll
    for (int i = 0; i < 2; i++)
#pragma unroll
        for (int j = 0; j < 8; j++)
#pragma unroll
            for (int q = 0; q < 4; q++) acc[i][j][q] = 0.f;

    const int lr = t >> 2;           // 0..63
    const int lc = (t & 3) * 8;      // 0,8,16,24

    const int a_r = lane & 15, a_c = (lane >> 4) * 8;
    const int b_r = ((lane >> 4) & 1) * 8 + (lane & 7), b_c = ((lane >> 3) & 1) * 8;

    const int nk = K >> 5;
    for (int kc = 0; kc < nk; kc++) {
        const int kb = kc * 32;
#pragma unroll
        for (int half = 0; half < 2; half++) {
            int r = lr + half * 64;
            *(uint4*)&sA[0][r][lc] = *(const uint4*)(Ah + (size_t)(m0 + r) * K + kb + lc);
            *(uint4*)&sA[1][r][lc] = *(const uint4*)(Al + (size_t)(m0 + r) * K + kb + lc);
            *(uint4*)&sB[0][r][lc] = *(const uint4*)(Bh + (size_t)(n0 + r) * K + kb + lc);
            *(uint4*)&sB[1][r][lc] = *(const uint4*)(Bl + (size_t)(n0 + r) * K + kb + lc);
        }
        __syncthreads();
#pragma unroll
        for (int kk = 0; kk < 2; kk++) {
            const int k0 = kk * 16;
            uint32_t afh[2][4], afl[2][4];
#pragma unroll
            for (int mt = 0; mt < 2; mt++) {
                int row = warp_m * 32 + mt * 16 + a_r;
                ldsm4(afh[mt], smem_u32(&sA[0][row][k0 + a_c]));
                ldsm4(afl[mt], smem_u32(&sA[1][row][k0 + a_c]));
            }
            uint32_t bfh[8][2], bfl[8][2];
#pragma unroll
            for (int np = 0; np < 4; np++) {
                int row = warp_n * 64 + np * 16 + b_r;
                uint32_t r4[4];
                ldsm4(r4, smem_u32(&sB[0][row][k0 + b_c]));
                bfh[np*2][0] = r4[0]; bfh[np*2][1] = r4[1];
                bfh[np*2+1][0] = r4[2]; bfh[np*2+1][1] = r4[3];
                ldsm4(r4, smem_u32(&sB[1][row][k0 + b_c]));
                bfl[np*2][0] = r4[0]; bfl[np*2][1] = r4[1];
                bfl[np*2+1][0] = r4[2]; bfl[np*2+1][1] = r4[3];
            }
#pragma unroll
            for (int mt = 0; mt < 2; mt++)
#pragma unroll
                for (int nt = 0; nt < 8; nt++) {
                    mma16816(acc[mt][nt], afh[mt], bfh[nt]);
                    mma16816(acc[mt][nt], afh[mt], bfl[nt]);
                    mma16816(acc[mt][nt], afl[mt], bfh[nt]);
                }
        }
        __syncthreads();
    }

    // epilogue: fragment -> gmem; WS: also emit bf16 splits of result
#pragma unroll
    for (int mt = 0; mt < 2; mt++) {
        int r0 = m0 + warp_m * 32 + mt * 16 + (lane >> 2);
#pragma unroll
        for (int nt = 0; nt < 8; nt++) {
            int cc = n0 + warp_n * 64 + nt * 8 + (lane & 3) * 2;
            float* p0 = C + (size_t)r0 * N + cc;
            float* p1 = p0 + (size_t)8 * N;
            float2 v0 = make_float2(acc[mt][nt][0], acc[mt][nt][1]);
            float2 v1 = make_float2(acc[mt][nt][2], acc[mt][nt][3]);
            if (RES) {
                float2 c0 = *(const float2*)p0, c1 = *(const float2*)p1;
                v0.x += c0.x; v0.y += c0.y; v1.x += c1.x; v1.y += c1.y;
            }
            *(float2*)p0 = v0;
            *(float2*)p1 = v1;
            if (WS) {
                __nv_bfloat162 h2, l2;
                split2(v0.x, v0.y, h2, l2);
                *(__nv_bfloat162*)(Oh + (size_t)r0 * N + cc) = h2;
                *(__nv_bfloat162*)(Ol + (size_t)r0 * N + cc) = l2;
                split2(v1.x, v1.y, h2, l2);
                *(__nv_bfloat162*)(Oh + (size_t)(r0 + 8) * N + cc) = h2;
                *(__nv_bfloat162*)(Ol + (size_t)(r0 + 8) * N + cc) = l2;
            }
        }
    }
}

// ---- probe ----
__device__ __forceinline__ float hashf(unsigned v) {
    v ^= v >> 16; v *= 0x7feb352dU; v ^= v >> 15; v *= 0x846ca68bU; v ^= v >> 16;
    return (float)(int)(v & 0xFFFF) * (1.f / 32768.f) - 1.f;
}
__global__ void probe_init2() {
    int i = blockIdx.x * 256 + threadIdx.x;
    float v = hashf(i * 2654435761u + 98765u);
    if (i < 128 * 192) g_pA2[i] = v;
    else               g_pW2[i - 128 * 192] = v;
}
__global__ void probe_check2() {
    int t = threadIdx.x, ok = 1;
    for (int e = t; e < 128 * 128; e += 256) {
        int m = e >> 7, n = e & 127;
        float ref = 0.f;
        for (int k = 0; k < 192; k++)
            ref = fmaf(g_pA2[m * 192 + k], g_pW2[k * 128 + n], ref);
        if (fabsf(g_pC2[e] - ref) > 2e-3f * fmaxf(fabsf(ref), 1.f)) ok = 0;
    }
    ok = __syncthreads_and(ok);
    if (t == 0) g_use_mma = ok;
}

// ---- f32x2 fallback GEMM (proven R5/R7) ----
#define AS(bf,k,i) As[(((bf)<<4)+(k))][i]
#define BS(bf,k,i) Bs[(((bf)<<4)+(k))][i]
template<int RES>
__global__ __launch_bounds__(256) void sgemm_f32x2(int K, int N,
        const float* __restrict__ A, const float* __restrict__ B, float* __restrict__ C)
{
    if (g_use_mma == 1) return;
    __shared__ __align__(16) float As[32][132];
    __shared__ __align__(16) float Bs[32][132];
    const float* Ap = A + (size_t)blockIdx.y * 128 * K;
    const float* Bp = B + blockIdx.x * 128;
    float*       Cp = C + (size_t)blockIdx.y * 128 * N + blockIdx.x * 128;
    const int tid = threadIdx.x;
    const int aRow = tid >> 2, aCol = (tid & 3) * 4;
    const int bRow = tid >> 5, bCol = (tid & 31) * 4;
    const int tr = (tid >> 4) * 8, tc = (tid & 15) * 8;
    float2 acc2[4][8];
#pragma unroll
    for (int p = 0; p < 4; p++)
#pragma unroll
        for (int j = 0; j < 8; j++) acc2[p][j] = make_float2(0.f, 0.f);
    auto compute = [&](int cb) {
#pragma unroll
        for (int k = 0; k < 16; k++) {
            float4 a0 = *(const float4*)&AS(cb, k, tr);
            float4 a1 = *(const float4*)&AS(cb, k, tr + 4);
            float4 b0 = *(const float4*)&BS(cb, k, tc);
            float4 b1 = *(const float4*)&BS(cb, k, tc + 4);
            float2 ap[4] = {make_float2(a0.x,a0.y), make_float2(a0.z,a0.w),
                            make_float2(a1.x,a1.y), make_float2(a1.z,a1.w)};
            float bv[8] = {b0.x,b0.y,b0.z,b0.w,b1.x,b1.y,b1.z,b1.w};
#pragma unroll
            for (int p = 0; p < 4; p++)
#pragma unroll
                for (int j = 0; j < 8; j++)
                    acc2[p][j] = ffma2f(acc2[p][j], ap[p], make_float2(bv[j], bv[j]));
        }
    };
    float4 ra0 = *(const float4*)(Ap + (size_t)aRow * K + aCol);
    float4 ra1 = *(const float4*)(Ap + (size_t)(aRow + 64) * K + aCol);
    float4 rb0 = *(const float4*)(Bp + (size_t)bRow * N + bCol);
    float4 rb1 = *(const float4*)(Bp + (size_t)(bRow + 8) * N + bCol);
    AS(0,aCol+0,aRow)=ra0.x; AS(0,aCol+1,aRow)=ra0.y; AS(0,aCol+2,aRow)=ra0.z; AS(0,aCol+3,aRow)=ra0.w;
    AS(0,aCol+0,aRow+64)=ra1.x; AS(0,aCol+1,aRow+64)=ra1.y; AS(0,aCol+2,aRow+64)=ra1.z; AS(0,aCol+3,aRow+64)=ra1.w;
    *(float4*)&BS(0,bRow,bCol)=rb0; *(float4*)&BS(0,bRow+8,bCol)=rb1;
    __syncthreads();
    const int nk = K >> 4;
    for (int s = 1; s < nk; s++) {
        ra0 = *(const float4*)(Ap + (size_t)aRow * K + s * 16 + aCol);
        ra1 = *(const float4*)(Ap + (size_t)(aRow + 64) * K + s * 16 + aCol);
        rb0 = *(const float4*)(Bp + (size_t)(s * 16 + bRow) * N + bCol);
        rb1 = *(const float4*)(Bp + (size_t)(s * 16 + bRow + 8) * N + bCol);
        compute((s - 1) & 1);
        const int nb = s & 1;
        AS(nb,aCol+0,aRow)=ra0.x; AS(nb,aCol+1,aRow)=ra0.y; AS(nb,aCol+2,aRow)=ra0.z; AS(nb,aCol+3,aRow)=ra0.w;
        AS(nb,aCol+0,aRow+64)=ra1.x; AS(nb,aCol+1,aRow+64)=ra1.y; AS(nb,aCol+2,aRow+64)=ra1.z; AS(nb,aCol+3,aRow+64)=ra1.w;
        *(float4*)&BS(nb,bRow,bCol)=rb0; *(float4*)&BS(nb,bRow+8,bCol)=rb1;
        __syncthreads();
    }
    compute((nk - 1) & 1);
#pragma unroll
    for (int p = 0; p < 4; p++) {
        float* r0 = Cp + (size_t)(tr + 2 * p) * N + tc;
        float* r1 = r0 + N;
        float4 v0 = make_float4(acc2[p][0].x, acc2[p][1].x, acc2[p][2].x, acc2[p][3].x);
        float4 v1 = make_float4(acc2[p][4].x, acc2[p][5].x, acc2[p][6].x, acc2[p][7].x);
        float4 w0 = make_float4(acc2[p][0].y, acc2[p][1].y, acc2[p][2].y, acc2[p][3].y);
        float4 w1 = make_float4(acc2[p][4].y, acc2[p][5].y, acc2[p][6].y, acc2[p][7].y);
        if (RES) {
            float4 c0 = *(const float4*)r0, c1 = *(const float4*)(r0 + 4);
            float4 d0 = *(const float4*)r1, d1 = *(const float4*)(r1 + 4);
            v0.x+=c0.x; v0.y+=c0.y; v0.z+=c0.z; v0.w+=c0.w;
            v1.x+=c1.x; v1.y+=c1.y; v1.z+=c1.z; v1.w+=c1.w;
            w0.x+=d0.x; w0.y+=d0.y; w0.z+=d0.z; w0.w+=d0.w;
            w1.x+=d1.x; w1.y+=d1.y; w1.z+=d1.z; w1.w+=d1.w;
        }
        *(float4*)r0 = v0; *(float4*)(r0 + 4) = v1;
        *(float4*)r1 = w0; *(float4*)(r1 + 4) = w1;
    }
}

// ---- conv + silu ----
__global__ void conv_silu_kernel(const float* __restrict__ cw, const float* __restrict__ cb)
{
    int idx = blockIdx.x * 256 + threadIdx.x;
    int d = idx & (DI - 1);
    int bt = idx >> 10;
    int t = bt & (LSEQ - 1);
    float acc = cb[d];
    const float* base = g_xz + (size_t)bt * (2 * DI) + d;
#pragma unroll
    for (int j = 0; j < KC; j++) {
        int tt = t - (KC - 1) + j;
        if (tt >= 0) acc += base[(size_t)(j - (KC - 1)) * (2 * DI)] * cw[d * KC + j];
    }
    g_u[idx] = acc * (1.f / (1.f + __expf(-acc)));
}

// ---- dbl = u @ Wx ----
__global__ __launch_bounds__(256) void gemm_dbl_kernel(const float* __restrict__ B)
{
    __shared__ float As[32][33];
    __shared__ float Bs[32][49];
    int tid = threadIdx.x;
    int m0 = blockIdx.x * 32;
    int tm = (tid >> 4) * 2, tn = (tid & 15) * 3;
    float acc[2][3] = {};
    int aRow = tid >> 3, aCol = (tid & 7) * 4;
    for (int k0 = 0; k0 < DI; k0 += 32) {
        float4 av = *(const float4*)(g_u + (size_t)(m0 + aRow) * DI + k0 + aCol);
        As[aCol+0][aRow]=av.x; As[aCol+1][aRow]=av.y; As[aCol+2][aRow]=av.z; As[aCol+3][aRow]=av.w;
#pragma unroll
        for (int p = 0; p < 6; p++) {
            int i2 = p * 256 + tid;
            Bs[i2 / DXP][i2 % DXP] = B[(size_t)(k0 + i2 / DXP) * DXP + i2 % DXP];
        }
        __syncthreads();
#pragma unroll
        for (int k = 0; k < 32; k++) {
            float a0 = As[k][tm], a1 = As[k][tm + 1];
            float b0 = Bs[k][tn], b1 = Bs[k][tn + 1], b2 = Bs[k][tn + 2];
            acc[0][0]+=a0*b0; acc[0][1]+=a0*b1; acc[0][2]+=a0*b2;
            acc[1][0]+=a1*b0; acc[1][1]+=a1*b1; acc[1][2]+=a1*b2;
        }
        __syncthreads();
    }
#pragma unroll
    for (int i = 0; i < 2; i++)
#pragma unroll
        for (int j = 0; j < 3; j++)
            g_dbl[(size_t)(m0 + tm + i) * DXP + tn + j] = acc[i][j];
}

// ---- delta = softplus(dt @ Wdt + b) ----
__global__ __launch_bounds__(256) void gemm_delta_kernel(const float* __restrict__ W,
                                                         const float* __restrict__ bias)
{
    __shared__ float dts[64][DTR];
    __shared__ float ws[DTR][128];
    int tid = threadIdx.x;
    int m0 = blockIdx.y * 64, n0 = blockIdx.x * 128;
#pragma unroll
    for (int p = 0; p < 8; p++) {
        int i2 = p * 256 + tid;
        dts[i2 >> 5][i2 & 31] = g_dbl[(size_t)(m0 + (i2 >> 5)) * DXP + (i2 & 31)];
    }
#pragma unroll
    for (int p = 0; p < 16; p++) {
        int i2 = p * 256 + tid;
        ws[i2 >> 7][i2 & 127] = W[(size_t)(i2 >> 7) * DI + n0 + (i2 & 127)];
    }
    __syncthreads();
    int tx = tid & 31, ty = tid >> 5, nl = tx * 4;
    float4 bv = *(const float4*)&bias[n0 + nl];
#pragma unroll
    for (int rr = 0; rr < 8; rr++) {
        int r = ty * 8 + rr;
        float ax = 0, ay = 0, az = 0, aw = 0;
#pragma unroll
        for (int k = 0; k < DTR; k++) {
            float dv = dts[r][k];
            float4 wv = *(const float4*)&ws[k][nl];
            ax += dv*wv.x; ay += dv*wv.y; az += dv*wv.z; aw += dv*wv.w;
        }
        float4 o;
        o.x = softplus_f(ax + bv.x); o.y = softplus_f(ay + bv.y);
        o.z = softplus_f(az + bv.z); o.w = softplus_f(aw + bv.w);
        *(float4*)&g_delta[(size_t)(m0 + r) * DI + n0 + nl] = o;
    }
}

// ---- selective scan ----
__device__ __forceinline__ bool load_a_fast(const float* __restrict__ A_log, int d,
                                            float* a, float& a0) {
#pragma unroll
    for (int n = 0; n < DS; n++) a[n] = -__expf(A_log[d * DS + n]);
    a0 = a[0];
    bool fast = true;
#pragma unroll
    for (int n = 0; n < DS; n++) {
        float ideal = (n + 1) * a0;
        if (fabsf(a[n] - ideal) > 1e-5f * fabsf(ideal)) fast = false;
    }
    return fast;
}
__global__ void scan_pass1(const float* __restrict__ A_log)
{
    int idx = blockIdx.x * 256 + threadIdx.x;
    int bd = idx & (BD - 1), c = idx >> 12, b = bd >> 10, d = bd & (DI - 1);
    float a[DS], a0;
    bool fast = load_a_fast(A_log, d, a, a0);
    float h[DS] = {};
    float ds = 0.f;
    int t0 = c * LCH;
    const float* dp = g_delta + ((size_t)(b * LSEQ + t0)) * DI + d;
    const float* up = g_u     + ((size_t)(b * LSEQ + t0)) * DI + d;
    const float* bp = g_dbl   + ((size_t)(b * LSEQ + t0)) * DXP + DTR;
    if (fast) {
        for (int t = 0; t < LCH; t++) {
            float dlt = *dp, uu = *up;
            ds += dlt;
            float du = dlt * uu, E = __expf(a0 * dlt), e = E;
#pragma unroll
            for (int n = 0; n < DS; n++) { h[n] = e * h[n] + du * bp[n]; e *= E; }
            dp += DI; up += DI; bp += DXP;
        }
    } else {
        for (int t = 0; t < LCH; t++) {
            float dlt = *dp, uu = *up;
            ds += dlt;
            float du = dlt * uu;
#pragma unroll
            for (int n = 0; n < DS; n++) h[n] = __expf(a[n] * dlt) * h[n] + du * bp[n];
            dp += DI; up += DI; bp += DXP;
        }
    }
    float* sp = g_s + (size_t)(bd * NCHUNK + c) * DS;
#pragma unroll
    for (int n = 0; n < DS; n++) sp[n] = h[n];
    g_dsum[bd * NCHUNK + c] = ds;
}
__global__ void scan_pass2(const float* __restrict__ A_log)
{
    int bd = blockIdx.x * 256 + threadIdx.x;
    int d = bd & (DI - 1);
    float a[DS];
#pragma unroll
    for (int n = 0; n < DS; n++) a[n] = -__expf(A_log[d * DS + n]);
    float h[DS] = {};
    for (int c = 0; c < NCHUNK; c++) {
        float* hp = g_hin + (size_t)(bd * NCHUNK + c) * DS;
#pragma unroll
        for (int n = 0; n < DS; n++) hp[n] = h[n];
        float ds = g_dsum[bd * NCHUNK + c];
        const float* sp = g_s + (size_t)(bd * NCHUNK + c) * DS;
#pragma unroll
        for (int n = 0; n < DS; n++) h[n] = __expf(a[n] * ds) * h[n] + sp[n];
    }
}
// pass3: emits gated ys + (if mma) fused bf16 splits of ys
__global__ void scan_pass3(const float* __restrict__ A_log, const float* __restrict__ Dvec)
{
    int idx = blockIdx.x * 256 + threadIdx.x;
    int bd = idx & (BD - 1), c = idx >> 12, b = bd >> 10, d = bd & (DI - 1);
    const int wr_split = (g_use_mma == 1);
    float a[DS], a0;
    bool fast = load_a_fast(A_log, d, a, a0);
    float h[DS];
    const float* hp = g_hin + (size_t)(bd * NCHUNK + c) * DS;
#pragma unroll
    for (int n = 0; n < DS; n++) h[n] = hp[n];
    float Dd = Dvec[d];
    int t0 = c * LCH;
    const float* dp = g_delta + ((size_t)(b * LSEQ + t0)) * DI + d;
    const float* up = g_u     + ((size_t)(b * LSEQ + t0)) * DI + d;
    const float* bp = g_dbl   + ((size_t)(b * LSEQ + t0)) * DXP + DTR;
    const float* zp = g_xz    + ((size_t)(b * LSEQ + t0)) * (2 * DI) + DI + d;
    float*       yp = g_ys    + ((size_t)(b * LSEQ + t0)) * DI + d;
    for (int t = 0; t < LCH; t++) {
        float dlt = *dp, uu = *up;
        float du = dlt * uu, acc = 0.f;
        if (fast) {
            float E = __expf(a0 * dlt), e = E;
#pragma unroll
            for (int n = 0; n < DS; n++) {
                h[n] = e * h[n] + du * bp[n];
                acc += h[n] * bp[DS + n];
                e *= E;
            }
        } else {
#pragma unroll
            for (int n = 0; n < DS; n++) {
                h[n] = __expf(a[n] * dlt) * h[n] + du * bp[n];
                acc += h[n] * bp[DS + n];
            }
        }
        float zv = *zp;
        float val = (acc + uu * Dd) * (zv / (1.f + __expf(-zv)));
        *yp = val;
        if (wr_split) {
            size_t off = (size_t)(yp - g_ys);
            __nv_bfloat16 hh = __float2bfloat16(val);
            g_Ch[off] = hh;
            g_Cl[off] = __float2bfloat16(val - __bfloat162float(hh));
        }
        dp += DI; up += DI; bp += DXP; zp += 2 * DI; yp += DI;
    }
}

// ---- pool + classifier ----
__global__ void pool_kernel()
{
    int idx = blockIdx.x * 256 + threadIdx.x;   // 8192
    int s = idx >> 11, r = idx & 2047, b = r >> 9, m = r & (DM - 1);
    const float* p = g_x + ((size_t)b * LSEQ + s * (LSEQ / 4)) * DM + m;
    float sum = 0.f;
#pragma unroll 4
    for (int t = 0; t < LSEQ / 4; t++) { sum += *p; p += DM; }
    g_pool4[idx] = sum;
}
__global__ void cls_kernel(const float* __restrict__ cw, const float* __restrict__ cb,
                           float* __restrict__ out)
{
    int tid = threadIdx.x;
    if (tid < BATCH * NCLS) {
        int b = tid / NCLS, c2 = tid % NCLS;
        float s = 0.f;
        for (int k = 0; k < DM; k++) {
            float pooled = g_pool4[b * DM + k] + g_pool4[2048 + b * DM + k]
                         + g_pool4[4096 + b * DM + k] + g_pool4[6144 + b * DM + k];
            s += pooled * cw[k * NCLS + c2];
        }
        out[tid] = cb[c2] + s * (1.f / LSEQ);
    }
}

// ---- launch ----
extern "C" void kernel_launch(void* const* d_in, const int* in_sizes, int n_in,
                              void* d_out, int out_size)
{
    const float* x    = (const float*)d_in[0];
    const float* Wi   = (const float*)d_in[1];
    const float* cw   = (const float*)d_in[2];
    const float* cb   = (const float*)d_in[3];
    const float* Wx   = (const float*)d_in[4];
    const float* Wdt  = (const float*)d_in[5];
    const float* bdt  = (const float*)d_in[6];
    const float* Alog = (const float*)d_in[7];
    const float* Dv   = (const float*)d_in[8];
    const float* Wo   = (const float*)d_in[9];
    const float* clsw = (const float*)d_in[10];
    const float* clsb = (const float*)d_in[11];
    float* out = (float*)d_out;

    float *px, *pxz, *pys, *pA2, *pW2, *pC2;
    __nv_bfloat16 *pAh, *pAl, *pCh, *pCl, *pBh, *pBl;
    cudaGetSymbolAddress((void**)&px,  g_x);
    cudaGetSymbolAddress((void**)&pxz, g_xz);
    cudaGetSymbolAddress((void**)&pys, g_ys);
    cudaGetSymbolAddress((void**)&pA2, g_pA2);
    cudaGetSymbolAddress((void**)&pW2, g_pW2);
    cudaGetSymbolAddress((void**)&pC2, g_pC2);
    cudaGetSymbolAddress((void**)&pAh, g_Ah);
    cudaGetSymbolAddress((void**)&pAl, g_Al);
    cudaGetSymbolAddress((void**)&pCh, g_Ch);
    cudaGetSymbolAddress((void**)&pCl, g_Cl);
    cudaGetSymbolAddress((void**)&pBh, g_Bh);
    cudaGetSymbolAddress((void**)&pBl, g_Bl);

    // probe: run the REAL HMMA kernel on 128x192x128 (6 K-chunks), verify on device
    probe_init2<<<192, 256>>>();
    split_a_kernel<<<24, 256>>>(pA2, pAh, pAl);
    split_bt_kernel<<<dim3(4, 6), dim3(32, 8)>>>(pW2, 192, 128, pBh, pBl, 1);
    hmma_gemm<0,0><<<dim3(1, 1), 256>>>(192, 128, pAh, pAl, pBh, pBl, pC2,
                                        (__nv_bfloat16*)0, (__nv_bfloat16*)0, 1);
    probe_check2<<<1, 256>>>();

    // copy x (+ fused split of initial x when mma enabled)
    copy_x_kernel<<<(MROWS * DM) / 1024, 256>>>(x);

    for (int i = 0; i < NBLK; i++) {
        // in_proj: xz = x @ Wi   (A-splits already in g_Ah/g_Al)
        split_bt_kernel<<<dim3(2 * DI / 32, DM / 32), dim3(32, 8)>>>(
            Wi + (size_t)i * DM * 2 * DI, DM, 2 * DI, pBh, pBl, 0);
        hmma_gemm<0,0><<<dim3(2 * DI / 128, MROWS / 128), 256>>>(
            DM, 2 * DI, pAh, pAl, pBh, pBl, pxz, (__nv_bfloat16*)0, (__nv_bfloat16*)0, 0);
        sgemm_f32x2<0><<<dim3(2 * DI / 128, MROWS / 128), 256>>>(
            DM, 2 * DI, px, Wi + (size_t)i * DM * 2 * DI, pxz);

        conv_silu_kernel<<<(MROWS * DI) / 256, 256>>>(
            cw + (size_t)i * DI * KC, cb + (size_t)i * DI);
        gemm_dbl_kernel<<<MROWS / 32, 256>>>(Wx + (size_t)i * DI * DXP);
        gemm_delta_kernel<<<dim3(DI / 128, MROWS / 64), 256>>>(
            Wdt + (size_t)i * DTR * DI, bdt + (size_t)i * DI);
        scan_pass1<<<(BD * NCHUNK) / 256, 256>>>(Alog + (size_t)i * DI * DS);
        scan_pass2<<<BD / 256, 256>>>(Alog + (size_t)i * DI * DS);
        scan_pass3<<<(BD * NCHUNK) / 256, 256>>>(Alog + (size_t)i * DI * DS,
                                                 Dv + (size_t)i * DI);   // writes ys + splits

        // out_proj: x += ys @ Wo ; epilogue emits splits of the new x
        split_bt_kernel<<<dim3(DM / 32, DI / 32), dim3(32, 8)>>>(
            Wo + (size_t)i * DI * DM, DI, DM, pBh, pBl, 0);
        hmma_gemm<1,1><<<dim3(DM / 128, MROWS / 128), 256>>>(
            DI, DM, pCh, pCl, pBh, pBl, px, pAh, pAl, 0);
        sgemm_f32x2<1><<<dim3(DM / 128, MROWS / 128), 256>>>(
            DI, DM, pys, Wo + (size_t)i * DI * DM, px);
    }

    pool_kernel<<<(4 * BATCH * DM) / 256, 256>>>();
    cls_kernel<<<1, 64>>>(clsw, clsb, out);
}

// round 14
// speedup vs baseline: 1.1369x; 1.1369x over previous
#include <cuda_runtime.h>
#include <cuda_bf16.h>
#include <math.h>
#include <stdint.h>

#define NBLK   3
#define DM     512
#define DI     1024
#define DS     8
#define KC     4
#define LSEQ   2048
#define BATCH  4
#define NCLS   10
#define DTR    32
#define MROWS  (BATCH*LSEQ)
#define DXP    (DTR + 2*DS)
#define NCHUNK 16
#define LCH    (LSEQ/NCHUNK)
#define BD     (BATCH*DI)

__device__ float g_x[MROWS*DM];
__device__ float g_xz[MROWS*2*DI];
__device__ float g_u[MROWS*DI];
__device__ float g_delta[MROWS*DI];
__device__ float g_dbl[MROWS*DXP];
__device__ float g_ys[MROWS*DI];
__device__ float g_s[BD*NCHUNK*DS];
__device__ float g_hin[BD*NCHUNK*DS];
__device__ float g_dsum[BD*NCHUNK];
__device__ float g_pool4[4*BATCH*DM];
__device__ __nv_bfloat16 g_Ah[MROWS*DI];
__device__ __nv_bfloat16 g_Al[MROWS*DI];
__device__ __nv_bfloat16 g_Bh[2*DI*DI];
__device__ __nv_bfloat16 g_Bl[2*DI*DI];
__device__ float g_pA2[128*192];
__device__ float g_pW2[192*128];
__device__ float g_pC2[128*128];
__device__ int   g_use_mma;

__device__ __forceinline__ float softplus_f(float v) {
    return (v > 20.f) ? v : log1pf(expf(v));
}
union F2U { unsigned long long u; float2 f; };
__device__ __forceinline__ float2 ffma2f(float2 d, float2 a, float2 b) {
    F2U dd, aa, bb; dd.f = d; aa.f = a; bb.f = b;
    asm("fma.rn.f32x2 %0, %1, %2, %0;" : "+l"(dd.u) : "l"(aa.u), "l"(bb.u));
    return dd.f;
}
__device__ __forceinline__ uint32_t smem_u32(const void* p) {
    uint32_t a;
    asm("{ .reg .u64 t; cvta.to.shared.u64 t, %1; cvt.u32.u64 %0, t; }" : "=r"(a) : "l"(p));
    return a;
}
__device__ __forceinline__ void mma16816(float* c, const uint32_t* a, const uint32_t* b) {
    asm volatile("mma.sync.aligned.m16n8k16.row.col.f32.bf16.bf16.f32 "
        "{%0,%1,%2,%3}, {%4,%5,%6,%7}, {%8,%9}, {%0,%1,%2,%3};"
        : "+f"(c[0]), "+f"(c[1]), "+f"(c[2]), "+f"(c[3])
        : "r"(a[0]), "r"(a[1]), "r"(a[2]), "r"(a[3]), "r"(b[0]), "r"(b[1]));
}
__device__ __forceinline__ void ldsm4(uint32_t* r, uint32_t addr) {
    asm volatile("ldmatrix.sync.aligned.m8n8.x4.shared.b16 {%0,%1,%2,%3}, [%4];"
        : "=r"(r[0]), "=r"(r[1]), "=r"(r[2]), "=r"(r[3]) : "r"(addr));
}
__device__ __forceinline__ void cpasync16(uint32_t dst, const void* src) {
    asm volatile("cp.async.cg.shared.global [%0], [%1], 16;" :: "r"(dst), "l"(src));
}
#define CP_COMMIT() asm volatile("cp.async.commit_group;" ::: "memory")
#define CP_WAIT1()  asm volatile("cp.async.wait_group 1;" ::: "memory")
#define CP_WAIT0()  asm volatile("cp.async.wait_group 0;" ::: "memory")

__device__ __forceinline__ void split2(float a, float b, __nv_bfloat162& h2, __nv_bfloat162& l2) {
    __nv_bfloat16 ha = __float2bfloat16(a), hb = __float2bfloat16(b);
    h2 = __nv_bfloat162(ha, hb);
    l2 = __nv_bfloat162(__float2bfloat16(a - __bfloat162float(ha)),
                        __float2bfloat16(b - __bfloat162float(hb)));
}

__global__ void copy_x_kernel(const float* __restrict__ x) {
    int i = blockIdx.x * 256 + threadIdx.x;
    reinterpret_cast<float4*>(g_x)[i] = reinterpret_cast<const float4*>(x)[i];
}

// standalone A-split (R11 scheme)
__global__ void split_a_kernel(const float* __restrict__ in,
                               __nv_bfloat16* __restrict__ oh,
                               __nv_bfloat16* __restrict__ ol, int force) {
    if (!force && g_use_mma != 1) return;
    int i = blockIdx.x * 256 + threadIdx.x;
    float4 v = reinterpret_cast<const float4*>(in)[i];
    __nv_bfloat162 h0, l0, h1, l1;
    split2(v.x, v.y, h0, l0);
    split2(v.z, v.w, h1, l1);
    __nv_bfloat162* ph = reinterpret_cast<__nv_bfloat162*>(oh) + i * 2;
    __nv_bfloat162* pl = reinterpret_cast<__nv_bfloat162*>(ol) + i * 2;
    ph[0] = h0; ph[1] = h1; pl[0] = l0; pl[1] = l1;
}
// W[K][N] fp32 -> hi/lo bf16 [N][K]
__global__ void split_bt_kernel(const float* __restrict__ W, int K, int N,
                                __nv_bfloat16* __restrict__ oh,
                                __nv_bfloat16* __restrict__ ol, int force) {
    if (!force && g_use_mma != 1) return;
    __shared__ float tile[32][33];
    int tx = threadIdx.x, ty = threadIdx.y;
    int n0 = blockIdx.x * 32, k0 = blockIdx.y * 32;
#pragma unroll
    for (int j = 0; j < 4; j++)
        tile[ty + j * 8][tx] = W[(size_t)(k0 + ty + j * 8) * N + n0 + tx];
    __syncthreads();
#pragma unroll
    for (int j = 0; j < 4; j++) {
        int n = n0 + ty + j * 8;
        float v = tile[tx][ty + j * 8];
        __nv_bfloat16 h = __float2bfloat16(v);
        oh[(size_t)n * K + k0 + tx] = h;
        ol[(size_t)n * K + k0 + tx] = __float2bfloat16(v - __bfloat162float(h));
    }
}

// ---- HMMA bf16x3 GEMM with cp.async 2-stage pipeline (R12 GEMM, no fusion) ----
#define SPAD 40
#define TILE (128*SPAD)
#define HMMA_SMEM (8*TILE*2)   // 81920 B

__device__ __forceinline__ void stage_load(__nv_bfloat16* sm, int stage, int t,
        const __nv_bfloat16* __restrict__ Ah, const __nv_bfloat16* __restrict__ Al,
        const __nv_bfloat16* __restrict__ Bh, const __nv_bfloat16* __restrict__ Bl,
        int m0, int n0, int kb, int K)
{
    const __nv_bfloat16* srcs[4] = {Ah, Al, Bh, Bl};
    const int row0s[4] = {m0, m0, n0, n0};
#pragma unroll
    for (int q = 0; q < 4; q++) {
        __nv_bfloat16* dstb = sm + (stage * 4 + q) * TILE;
#pragma unroll
        for (int p = 0; p < 2; p++) {
            int g = p * 256 + t;
            int r = g >> 2, cb = (g & 3) * 8;
            cpasync16(smem_u32(dstb + r * SPAD + cb),
                      srcs[q] + (size_t)(row0s[q] + r) * K + kb + cb);
        }
    }
}

template<int RES>
__global__ __launch_bounds__(256, 2) void hmma_gemm(int K, int N,
        const __nv_bfloat16* __restrict__ Ah, const __nv_bfloat16* __restrict__ Al,
        const __nv_bfloat16* __restrict__ Bh, const __nv_bfloat16* __restrict__ Bl,
        float* __restrict__ C, int force)
{
    if (!force && g_use_mma != 1) return;
    extern __shared__ __nv_bfloat16 sm[];
    const int t = threadIdx.x;
    const int wid = t >> 5, lane = t & 31;
    const int warp_m = wid & 3, warp_n = wid >> 2;
    const int m0 = blockIdx.y * 128, n0 = blockIdx.x * 128;

    float acc[2][8][4];
#pragma unroll
    for (int i = 0; i < 2; i++)
#pragma unroll
        for (int j = 0; j < 8; j++)
#pragma unroll
            for (int q = 0; q < 4; q++) acc[i][j][q] = 0.f;

    const int a_r = lane & 15, a_c = (lane >> 4) * 8;
    const int b_r = ((lane >> 4) & 1) * 8 + (lane & 7), b_c = ((lane >> 3) & 1) * 8;

    auto compute = [&](int stage) {
        const __nv_bfloat16* sAh = sm + (stage * 4 + 0) * TILE;
        const __nv_bfloat16* sAl = sm + (stage * 4 + 1) * TILE;
        const __nv_bfloat16* sBh = sm + (stage * 4 + 2) * TILE;
        const __nv_bfloat16* sBl = sm + (stage * 4 + 3) * TILE;
#pragma unroll
        for (int kk = 0; kk < 2; kk++) {
            const int k0 = kk * 16;
            uint32_t afh[2][4], afl[2][4];
#pragma unroll
            for (int mt = 0; mt < 2; mt++) {
                int row = warp_m * 32 + mt * 16 + a_r;
                ldsm4(afh[mt], smem_u32(sAh + row * SPAD + k0 + a_c));
                ldsm4(afl[mt], smem_u32(sAl + row * SPAD + k0 + a_c));
            }
            uint32_t bfh[8][2], bfl[8][2];
#pragma unroll
            for (int np = 0; np < 4; np++) {
                int row = warp_n * 64 + np * 16 + b_r;
                uint32_t r4[4];
                ldsm4(r4, smem_u32(sBh + row * SPAD + k0 + b_c));
                bfh[np*2][0] = r4[0]; bfh[np*2][1] = r4[1];
                bfh[np*2+1][0] = r4[2]; bfh[np*2+1][1] = r4[3];
                ldsm4(r4, smem_u32(sBl + row * SPAD + k0 + b_c));
                bfl[np*2][0] = r4[0]; bfl[np*2][1] = r4[1];
                bfl[np*2+1][0] = r4[2]; bfl[np*2+1][1] = r4[3];
            }
#pragma unroll
            for (int mt = 0; mt < 2; mt++)
#pragma unroll
                for (int nt = 0; nt < 8; nt++) {
                    mma16816(acc[mt][nt], afh[mt], bfh[nt]);
                    mma16816(acc[mt][nt], afh[mt], bfl[nt]);
                    mma16816(acc[mt][nt], afl[mt], bfh[nt]);
                }
        }
    };

    const int nk = K >> 5;
    stage_load(sm, 0, t, Ah, Al, Bh, Bl, m0, n0, 0, K);
    CP_COMMIT();
    for (int kc = 0; kc < nk; kc++) {
        if (kc + 1 < nk) {
            stage_load(sm, (kc + 1) & 1, t, Ah, Al, Bh, Bl, m0, n0, (kc + 1) * 32, K);
            CP_COMMIT();
            CP_WAIT1();
        } else {
            CP_WAIT0();
        }
        __syncthreads();
        compute(kc & 1);
        __syncthreads();
    }

#pragma unroll
    for (int mt = 0; mt < 2; mt++) {
        int r0 = m0 + warp_m * 32 + mt * 16 + (lane >> 2);
#pragma unroll
        for (int nt = 0; nt < 8; nt++) {
            int cc = n0 + warp_n * 64 + nt * 8 + (lane & 3) * 2;
            float* p0 = C + (size_t)r0 * N + cc;
            float* p1 = p0 + (size_t)8 * N;
            float2 v0 = make_float2(acc[mt][nt][0], acc[mt][nt][1]);
            float2 v1 = make_float2(acc[mt][nt][2], acc[mt][nt][3]);
            if (RES) {
                float2 c0 = *(const float2*)p0, c1 = *(const float2*)p1;
                v0.x += c0.x; v0.y += c0.y; v1.x += c1.x; v1.y += c1.y;
            }
            *(float2*)p0 = v0;
            *(float2*)p1 = v1;
        }
    }
}

// ---- probe ----
__device__ __forceinline__ float hashf(unsigned v) {
    v ^= v >> 16; v *= 0x7feb352dU; v ^= v >> 15; v *= 0x846ca68bU; v ^= v >> 16;
    return (float)(int)(v & 0xFFFF) * (1.f / 32768.f) - 1.f;
}
__global__ void probe_init2() {
    int i = blockIdx.x * 256 + threadIdx.x;
    float v = hashf(i * 2654435761u + 98765u);
    if (i < 128 * 192) g_pA2[i] = v;
    else               g_pW2[i - 128 * 192] = v;
}
__global__ void probe_check2() {
    int t = threadIdx.x, ok = 1;
    for (int e = t; e < 128 * 128; e += 256) {
        int m = e >> 7, n = e & 127;
        float ref = 0.f;
        for (int k = 0; k < 192; k++)
            ref = fmaf(g_pA2[m * 192 + k], g_pW2[k * 128 + n], ref);
        if (fabsf(g_pC2[e] - ref) > 2e-3f * fmaxf(fabsf(ref), 1.f)) ok = 0;
    }
    ok = __syncthreads_and(ok);
    if (t == 0) g_use_mma = ok;
}

// ---- f32x2 fallback GEMM (proven R5/R7) ----
#define AS(bf,k,i) As[(((bf)<<4)+(k))][i]
#define BS(bf,k,i) Bs[(((bf)<<4)+(k))][i]
template<int RES>
__global__ __launch_bounds__(256) void sgemm_f32x2(int K, int N,
        const float* __restrict__ A, const float* __restrict__ B, float* __restrict__ C)
{
    if (g_use_mma == 1) return;
    __shared__ __align__(16) float As[32][132];
    __shared__ __align__(16) float Bs[32][132];
    const float* Ap = A + (size_t)blockIdx.y * 128 * K;
    const float* Bp = B + blockIdx.x * 128;
    float*       Cp = C + (size_t)blockIdx.y * 128 * N + blockIdx.x * 128;
    const int tid = threadIdx.x;
    const int aRow = tid >> 2, aCol = (tid & 3) * 4;
    const int bRow = tid >> 5, bCol = (tid & 31) * 4;
    const int tr = (tid >> 4) * 8, tc = (tid & 15) * 8;
    float2 acc2[4][8];
#pragma unroll
    for (int p = 0; p < 4; p++)
#pragma unroll
        for (int j = 0; j < 8; j++) acc2[p][j] = make_float2(0.f, 0.f);
    auto compute = [&](int cb) {
#pragma unroll
        for (int k = 0; k < 16; k++) {
            float4 a0 = *(const float4*)&AS(cb, k, tr);
            float4 a1 = *(const float4*)&AS(cb, k, tr + 4);
            float4 b0 = *(const float4*)&BS(cb, k, tc);
            float4 b1 = *(const float4*)&BS(cb, k, tc + 4);
            float2 ap[4] = {make_float2(a0.x,a0.y), make_float2(a0.z,a0.w),
                            make_float2(a1.x,a1.y), make_float2(a1.z,a1.w)};
            float bv[8] = {b0.x,b0.y,b0.z,b0.w,b1.x,b1.y,b1.z,b1.w};
#pragma unroll
            for (int p = 0; p < 4; p++)
#pragma unroll
                for (int j = 0; j < 8; j++)
                    acc2[p][j] = ffma2f(acc2[p][j], ap[p], make_float2(bv[j], bv[j]));
        }
    };
    float4 ra0 = *(const float4*)(Ap + (size_t)aRow * K + aCol);
    float4 ra1 = *(const float4*)(Ap + (size_t)(aRow + 64) * K + aCol);
    float4 rb0 = *(const float4*)(Bp + (size_t)bRow * N + bCol);
    float4 rb1 = *(const float4*)(Bp + (size_t)(bRow + 8) * N + bCol);
    AS(0,aCol+0,aRow)=ra0.x; AS(0,aCol+1,aRow)=ra0.y; AS(0,aCol+2,aRow)=ra0.z; AS(0,aCol+3,aRow)=ra0.w;
    AS(0,aCol+0,aRow+64)=ra1.x; AS(0,aCol+1,aRow+64)=ra1.y; AS(0,aCol+2,aRow+64)=ra1.z; AS(0,aCol+3,aRow+64)=ra1.w;
    *(float4*)&BS(0,bRow,bCol)=rb0; *(float4*)&BS(0,bRow+8,bCol)=rb1;
    __syncthreads();
    const int nk = K >> 4;
    for (int s = 1; s < nk; s++) {
        ra0 = *(const float4*)(Ap + (size_t)aRow * K + s * 16 + aCol);
        ra1 = *(const float4*)(Ap + (size_t)(aRow + 64) * K + s * 16 + aCol);
        rb0 = *(const float4*)(Bp + (size_t)(s * 16 + bRow) * N + bCol);
        rb1 = *(const float4*)(Bp + (size_t)(s * 16 + bRow + 8) * N + bCol);
        compute((s - 1) & 1);
        const int nb = s & 1;
        AS(nb,aCol+0,aRow)=ra0.x; AS(nb,aCol+1,aRow)=ra0.y; AS(nb,aCol+2,aRow)=ra0.z; AS(nb,aCol+3,aRow)=ra0.w;
        AS(nb,aCol+0,aRow+64)=ra1.x; AS(nb,aCol+1,aRow+64)=ra1.y; AS(nb,aCol+2,aRow+64)=ra1.z; AS(nb,aCol+3,aRow+64)=ra1.w;
        *(float4*)&BS(nb,bRow,bCol)=rb0; *(float4*)&BS(nb,bRow+8,bCol)=rb1;
        __syncthreads();
    }
    compute((nk - 1) & 1);
#pragma unroll
    for (int p = 0; p < 4; p++) {
        float* r0 = Cp + (size_t)(tr + 2 * p) * N + tc;
        float* r1 = r0 + N;
        float4 v0 = make_float4(acc2[p][0].x, acc2[p][1].x, acc2[p][2].x, acc2[p][3].x);
        float4 v1 = make_float4(acc2[p][4].x, acc2[p][5].x, acc2[p][6].x, acc2[p][7].x);
        float4 w0 = make_float4(acc2[p][0].y, acc2[p][1].y, acc2[p][2].y, acc2[p][3].y);
        float4 w1 = make_float4(acc2[p][4].y, acc2[p][5].y, acc2[p][6].y, acc2[p][7].y);
        if (RES) {
            float4 c0 = *(const float4*)r0, c1 = *(const float4*)(r0 + 4);
            float4 d0 = *(const float4*)r1, d1 = *(const float4*)(r1 + 4);
            v0.x+=c0.x; v0.y+=c0.y; v0.z+=c0.z; v0.w+=c0.w;
            v1.x+=c1.x; v1.y+=c1.y; v1.z+=c1.z; v1.w+=c1.w;
            w0.x+=d0.x; w0.y+=d0.y; w0.z+=d0.z; w0.w+=d0.w;
            w1.x+=d1.x; w1.y+=d1.y; w1.z+=d1.z; w1.w+=d1.w;
        }
        *(float4*)r0 = v0; *(float4*)(r0 + 4) = v1;
        *(float4*)r1 = w0; *(float4*)(r1 + 4) = w1;
    }
}

// ---- conv + silu ----
__global__ void conv_silu_kernel(const float* __restrict__ cw, const float* __restrict__ cb)
{
    int idx = blockIdx.x * 256 + threadIdx.x;
    int d = idx & (DI - 1);
    int bt = idx >> 10;
    int t = bt & (LSEQ - 1);
    float acc = cb[d];
    const float* base = g_xz + (size_t)bt * (2 * DI) + d;
#pragma unroll
    for (int j = 0; j < KC; j++) {
        int tt = t - (KC - 1) + j;
        if (tt >= 0) acc += base[(size_t)(j - (KC - 1)) * (2 * DI)] * cw[d * KC + j];
    }
    g_u[idx] = acc * (1.f / (1.f + __expf(-acc)));
}

// ---- dbl = u @ Wx ----
__global__ __launch_bounds__(256) void gemm_dbl_kernel(const float* __restrict__ B)
{
    __shared__ float As[32][33];
    __shared__ float Bs[32][49];
    int tid = threadIdx.x;
    int m0 = blockIdx.x * 32;
    int tm = (tid >> 4) * 2, tn = (tid & 15) * 3;
    float acc[2][3] = {};
    int aRow = tid >> 3, aCol = (tid & 7) * 4;
    for (int k0 = 0; k0 < DI; k0 += 32) {
        float4 av = *(const float4*)(g_u + (size_t)(m0 + aRow) * DI + k0 + aCol);
        As[aCol+0][aRow]=av.x; As[aCol+1][aRow]=av.y; As[aCol+2][aRow]=av.z; As[aCol+3][aRow]=av.w;
#pragma unroll
        for (int p = 0; p < 6; p++) {
            int i2 = p * 256 + tid;
            Bs[i2 / DXP][i2 % DXP] = B[(size_t)(k0 + i2 / DXP) * DXP + i2 % DXP];
        }
        __syncthreads();
#pragma unroll
        for (int k = 0; k < 32; k++) {
            float a0 = As[k][tm], a1 = As[k][tm + 1];
            float b0 = Bs[k][tn], b1 = Bs[k][tn + 1], b2 = Bs[k][tn + 2];
            acc[0][0]+=a0*b0; acc[0][1]+=a0*b1; acc[0][2]+=a0*b2;
            acc[1][0]+=a1*b0; acc[1][1]+=a1*b1; acc[1][2]+=a1*b2;
        }
        __syncthreads();
    }
#pragma unroll
    for (int i = 0; i < 2; i++)
#pragma unroll
        for (int j = 0; j < 3; j++)
            g_dbl[(size_t)(m0 + tm + i) * DXP + tn + j] = acc[i][j];
}

// ---- delta = softplus(dt @ Wdt + b) ----
__global__ __launch_bounds__(256) void gemm_delta_kernel(const float* __restrict__ W,
                                                         const float* __restrict__ bias)
{
    __shared__ float dts[64][DTR];
    __shared__ float ws[DTR][128];
    int tid = threadIdx.x;
    int m0 = blockIdx.y * 64, n0 = blockIdx.x * 128;
#pragma unroll
    for (int p = 0; p < 8; p++) {
        int i2 = p * 256 + tid;
        dts[i2 >> 5][i2 & 31] = g_dbl[(size_t)(m0 + (i2 >> 5)) * DXP + (i2 & 31)];
    }
#pragma unroll
    for (int p = 0; p < 16; p++) {
        int i2 = p * 256 + tid;
        ws[i2 >> 7][i2 & 127] = W[(size_t)(i2 >> 7) * DI + n0 + (i2 & 127)];
    }
    __syncthreads();
    int tx = tid & 31, ty = tid >> 5, nl = tx * 4;
    float4 bv = *(const float4*)&bias[n0 + nl];
#pragma unroll
    for (int rr = 0; rr < 8; rr++) {
        int r = ty * 8 + rr;
        float ax = 0, ay = 0, az = 0, aw = 0;
#pragma unroll
        for (int k = 0; k < DTR; k++) {
            float dv = dts[r][k];
            float4 wv = *(const float4*)&ws[k][nl];
            ax += dv*wv.x; ay += dv*wv.y; az += dv*wv.z; aw += dv*wv.w;
        }
        float4 o;
        o.x = softplus_f(ax + bv.x); o.y = softplus_f(ay + bv.y);
        o.z = softplus_f(az + bv.z); o.w = softplus_f(aw + bv.w);
        *(float4*)&g_delta[(size_t)(m0 + r) * DI + n0 + nl] = o;
    }
}

// ---- selective scan ----
__device__ __forceinline__ bool load_a_fast(const float* __restrict__ A_log, int d,
                                            float* a, float& a0) {
#pragma unroll
    for (int n = 0; n < DS; n++) a[n] = -__expf(A_log[d * DS + n]);
    a0 = a[0];
    bool fast = true;
#pragma unroll
    for (int n = 0; n < DS; n++) {
        float ideal = (n + 1) * a0;
        if (fabsf(a[n] - ideal) > 1e-5f * fabsf(ideal)) fast = false;
    }
    return fast;
}
__global__ void scan_pass1(const float* __restrict__ A_log)
{
    int idx = blockIdx.x * 256 + threadIdx.x;
    int bd = idx & (BD - 1), c = idx >> 12, b = bd >> 10, d = bd & (DI - 1);
    float a[DS], a0;
    bool fast = load_a_fast(A_log, d, a, a0);
    float h[DS] = {};
    float ds = 0.f;
    int t0 = c * LCH;
    const float* dp = g_delta + ((size_t)(b * LSEQ + t0)) * DI + d;
    const float* up = g_u     + ((size_t)(b * LSEQ + t0)) * DI + d;
    const float* bp = g_dbl   + ((size_t)(b * LSEQ + t0)) * DXP + DTR;
    if (fast) {
        for (int t = 0; t < LCH; t++) {
            float dlt = *dp, uu = *up;
            ds += dlt;
            float du = dlt * uu, E = __expf(a0 * dlt), e = E;
#pragma unroll
            for (int n = 0; n < DS; n++) { h[n] = e * h[n] + du * bp[n]; e *= E; }
            dp += DI; up += DI; bp += DXP;
        }
    } else {
        for (int t = 0; t < LCH; t++) {
            float dlt = *dp, uu = *up;
            ds += dlt;
            float du = dlt * uu;
#pragma unroll
            for (int n = 0; n < DS; n++) h[n] = __expf(a[n] * dlt) * h[n] + du * bp[n];
            dp += DI; up += DI; bp += DXP;
        }
    }
    float* sp = g_s + (size_t)(bd * NCHUNK + c) * DS;
#pragma unroll
    for (int n = 0; n < DS; n++) sp[n] = h[n];
    g_dsum[bd * NCHUNK + c] = ds;
}
__global__ void scan_pass2(const float* __restrict__ A_log)
{
    int bd = blockIdx.x * 256 + threadIdx.x;
    int d = bd & (DI - 1);
    float a[DS];
#pragma unroll
    for (int n = 0; n < DS; n++) a[n] = -__expf(A_log[d * DS + n]);
    float h[DS] = {};
    for (int c = 0; c < NCHUNK; c++) {
        float* hp = g_hin + (size_t)(bd * NCHUNK + c) * DS;
#pragma unroll
        for (int n = 0; n < DS; n++) hp[n] = h[n];
        float ds = g_dsum[bd * NCHUNK + c];
        const float* sp = g_s + (size_t)(bd * NCHUNK + c) * DS;
#pragma unroll
        for (int n = 0; n < DS; n++) h[n] = __expf(a[n] * ds) * h[n] + sp[n];
    }
}
__global__ void scan_pass3(const float* __restrict__ A_log, const float* __restrict__ Dvec)
{
    int idx = blockIdx.x * 256 + threadIdx.x;
    int bd = idx & (BD - 1), c = idx >> 12, b = bd >> 10, d = bd & (DI - 1);
    float a[DS], a0;
    bool fast = load_a_fast(A_log, d, a, a0);
    float h[DS];
    const float* hp = g_hin + (size_t)(bd * NCHUNK + c) * DS;
#pragma unroll
    for (int n = 0; n < DS; n++) h[n] = hp[n];
    float Dd = Dvec[d];
    int t0 = c * LCH;
    const float* dp = g_delta + ((size_t)(b * LSEQ + t0)) * DI + d;
    const float* up = g_u     + ((size_t)(b * LSEQ + t0)) * DI + d;
    const float* bp = g_dbl   + ((size_t)(b * LSEQ + t0)) * DXP + DTR;
    const float* zp = g_xz    + ((size_t)(b * LSEQ + t0)) * (2 * DI) + DI + d;
    float*       yp = g_ys    + ((size_t)(b * LSEQ + t0)) * DI + d;
    if (fast) {
        for (int t = 0; t < LCH; t++) {
            float dlt = *dp, uu = *up;
            float du = dlt * uu, E = __expf(a0 * dlt), e = E, acc = 0.f;
#pragma unroll
            for (int n = 0; n < DS; n++) {
                h[n] = e * h[n] + du * bp[n];
                acc += h[n] * bp[DS + n];
                e *= E;
            }
            float zv = *zp;
            *yp = (acc + uu * Dd) * (zv / (1.f + __expf(-zv)));
            dp += DI; up += DI; bp += DXP; zp += 2 * DI; yp += DI;
        }
    } else {
        for (int t = 0; t < LCH; t++) {
            float dlt = *dp, uu = *up;
            float du = dlt * uu, acc = 0.f;
#pragma unroll
            for (int n = 0; n < DS; n++) {
                h[n] = __expf(a[n] * dlt) * h[n] + du * bp[n];
                acc += h[n] * bp[DS + n];
            }
            float zv = *zp;
            *yp = (acc + uu * Dd) * (zv / (1.f + __expf(-zv)));
            dp += DI; up += DI; bp += DXP; zp += 2 * DI; yp += DI;
        }
    }
}

// ---- pool + classifier ----
__global__ void pool_kernel()
{
    int idx = blockIdx.x * 256 + threadIdx.x;   // 8192
    int s = idx >> 11, r = idx & 2047, b = r >> 9, m = r & (DM - 1);
    const float* p = g_x + ((size_t)b * LSEQ + s * (LSEQ / 4)) * DM + m;
    float sum = 0.f;
#pragma unroll 4
    for (int t = 0; t < LSEQ / 4; t++) { sum += *p; p += DM; }
    g_pool4[idx] = sum;
}
__global__ void cls_kernel(const float* __restrict__ cw, const float* __restrict__ cb,
                           float* __restrict__ out)
{
    int tid = threadIdx.x;
    if (tid < BATCH * NCLS) {
        int b = tid / NCLS, c2 = tid % NCLS;
        float s = 0.f;
        for (int k = 0; k < DM; k++) {
            float pooled = g_pool4[b * DM + k] + g_pool4[2048 + b * DM + k]
                         + g_pool4[4096 + b * DM + k] + g_pool4[6144 + b * DM + k];
            s += pooled * cw[k * NCLS + c2];
        }
        out[tid] = cb[c2] + s * (1.f / LSEQ);
    }
}

// ---- launch ----
extern "C" void kernel_launch(void* const* d_in, const int* in_sizes, int n_in,
                              void* d_out, int out_size)
{
    const float* x    = (const float*)d_in[0];
    const float* Wi   = (const float*)d_in[1];
    const float* cw   = (const float*)d_in[2];
    const float* cb   = (const float*)d_in[3];
    const float* Wx   = (const float*)d_in[4];
    const float* Wdt  = (const float*)d_in[5];
    const float* bdt  = (const float*)d_in[6];
    const float* Alog = (const float*)d_in[7];
    const float* Dv   = (const float*)d_in[8];
    const float* Wo   = (const float*)d_in[9];
    const float* clsw = (const float*)d_in[10];
    const float* clsb = (const float*)d_in[11];
    float* out = (float*)d_out;

    float *px, *pxz, *pys, *pA2, *pW2, *pC2;
    __nv_bfloat16 *pAh, *pAl, *pBh, *pBl;
    cudaGetSymbolAddress((void**)&px,  g_x);
    cudaGetSymbolAddress((void**)&pxz, g_xz);
    cudaGetSymbolAddress((void**)&pys, g_ys);
    cudaGetSymbolAddress((void**)&pA2, g_pA2);
    cudaGetSymbolAddress((void**)&pW2, g_pW2);
    cudaGetSymbolAddress((void**)&pC2, g_pC2);
    cudaGetSymbolAddress((void**)&pAh, g_Ah);
    cudaGetSymbolAddress((void**)&pAl, g_Al);
    cudaGetSymbolAddress((void**)&pBh, g_Bh);
    cudaGetSymbolAddress((void**)&pBl, g_Bl);

    cudaFuncSetAttribute(hmma_gemm<0>, cudaFuncAttributeMaxDynamicSharedMemorySize, HMMA_SMEM);
    cudaFuncSetAttribute(hmma_gemm<1>, cudaFuncAttributeMaxDynamicSharedMemorySize, HMMA_SMEM);

    // probe: run the REAL pipelined HMMA kernel on 128x192x128 (6 K-chunks)
    probe_init2<<<192, 256>>>();
    split_a_kernel<<<24, 256>>>(pA2, pAh, pAl, 1);
    split_bt_kernel<<<dim3(4, 6), dim3(32, 8)>>>(pW2, 192, 128, pBh, pBl, 1);
    hmma_gemm<0><<<dim3(1, 1), 256, HMMA_SMEM>>>(192, 128, pAh, pAl, pBh, pBl, pC2, 1);
    probe_check2<<<1, 256>>>();

    copy_x_kernel<<<(MROWS * DM) / 1024, 256>>>(x);

    for (int i = 0; i < NBLK; i++) {
        // in_proj: xz = x @ Wi
        split_a_kernel<<<(MROWS * DM / 4) / 256, 256>>>(px, pAh, pAl, 0);
        split_bt_kernel<<<dim3(2 * DI / 32, DM / 32), dim3(32, 8)>>>(
            Wi + (size_t)i * DM * 2 * DI, DM, 2 * DI, pBh, pBl, 0);
        hmma_gemm<0><<<dim3(2 * DI / 128, MROWS / 128), 256, HMMA_SMEM>>>(
            DM, 2 * DI, pAh, pAl, pBh, pBl, pxz, 0);
        sgemm_f32x2<0><<<dim3(2 * DI / 128, MROWS / 128), 256>>>(
            DM, 2 * DI, px, Wi + (size_t)i * DM * 2 * DI, pxz);

        conv_silu_kernel<<<(MROWS * DI) / 256, 256>>>(
            cw + (size_t)i * DI * KC, cb + (size_t)i * DI);
        gemm_dbl_kernel<<<MROWS / 32, 256>>>(Wx + (size_t)i * DI * DXP);
        gemm_delta_kernel<<<dim3(DI / 128, MROWS / 64), 256>>>(
            Wdt + (size_t)i * DTR * DI, bdt + (size_t)i * DI);
        scan_pass1<<<(BD * NCHUNK) / 256, 256>>>(Alog + (size_t)i * DI * DS);
        scan_pass2<<<BD / 256, 256>>>(Alog + (size_t)i * DI * DS);
        scan_pass3<<<(BD * NCHUNK) / 256, 256>>>(Alog + (size_t)i * DI * DS,
                                                 Dv + (size_t)i * DI);

        // out_proj: x += ys @ Wo
        split_a_kernel<<<(MROWS * DI / 4) / 256, 256>>>(pys, pAh, pAl, 0);
        split_bt_kernel<<<dim3(DM / 32, DI / 32), dim3(32, 8)>>>(
            Wo + (size_t)i * DI * DM, DI, DM, pBh, pBl, 0);
        hmma_gemm<1><<<dim3(DM / 128, MROWS / 128), 256, HMMA_SMEM>>>(
            DI, DM, pAh, pAl, pBh, pBl, px, 0);
        sgemm_f32x2<1><<<dim3(DM / 128, MROWS / 128), 256>>>(
            DI, DM, pys, Wo + (size_t)i * DI * DM, px);
    }

    pool_kernel<<<(4 * BATCH * DM) / 256, 256>>>();
    cls_kernel<<<1, 64>>>(clsw, clsb, out);
}